// round 12
// baseline (speedup 1.0000x reference)
#include <cuda_runtime.h>

#define HPF 32
#define NBLK 20
#define HID 640
#define BATCHN 128
#define SEQ 512
#define INSZ 16
#define TPB 64             // 2 warps per CTA
#define NCTA 1280          // 20 j-blocks * 64 batch-pairs

// ---- packed fp32x2 helpers (sm_103a dual fp32) ----
__device__ __forceinline__ unsigned long long pk2(float a, float b) {
    unsigned long long r;
    asm("mov.b64 %0, {%1, %2};" : "=l"(r) : "f"(a), "f"(b));
    return r;
}
__device__ __forceinline__ float2 upk2(unsigned long long v) {
    float2 f;
    asm("mov.b64 {%0, %1}, %2;" : "=f"(f.x), "=f"(f.y) : "l"(v));
    return f;
}
__device__ __forceinline__ void fma2(unsigned long long& d,
                                     unsigned long long a, unsigned long long b) {
    asm("fma.rn.f32x2 %0, %1, %2, %0;" : "+l"(d) : "l"(a), "l"(b));
}
__device__ __forceinline__ float tanhapx(float x) {
    float r;
    asm("tanh.approx.f32 %0, %1;" : "=f"(r) : "f"(x));
    return r;
}

__global__ __launch_bounds__(TPB, 9)
void lstm_fused_kernel(const float* __restrict__ x,
                       const float* __restrict__ Ui, const float* __restrict__ Vi, const float* __restrict__ bi,
                       const float* __restrict__ Uf, const float* __restrict__ Vf, const float* __restrict__ bf,
                       const float* __restrict__ Uc, const float* __restrict__ Vc, const float* __restrict__ bc,
                       const float* __restrict__ Uo, const float* __restrict__ Vo, const float* __restrict__ bo,
                       float* __restrict__ out, long long out_size)
{
    // per-batch h stages (CTA-shared, written cooperatively by both warps)
    __shared__ __align__(16) float hs0[HPF];
    __shared__ __align__(16) float hs1[HPF];
    // staged x features (+1 pad for the final discarded phase-B prefetch)
    __shared__ __align__(16) float2 xs[2][SEQ + 1];

    const int tid  = threadIdx.x;
    const int w    = tid >> 5;
    const int lane = tid & 31;
    const int c    = lane & 15;       // local column within warp's half
    const int ha   = lane >> 4;       // m-half (0: m 0-15, 1: m 16-31)
    const int mb   = ha * 16;         // m base
    const int n    = w * 16 + c;      // column within j-block (0..31)
    const int j    = blockIdx.x % NBLK;
    const int grp  = blockIdx.x / NBLK;
    const int b0   = grp * 2;
    const int col  = j * HPF + n;

    const float* Vg[4] = {Vi, Vf, Vc, Vo};
    const float* Ug[4] = {Ui, Uf, Uc, Uo};
    const float* Bg[4] = {bi, bf, bc, bo};

    // ---- V blocks -> registers: only this lane's m-half, sigmoid gates pre-scaled by 0.5 ----
    // vr[g][q] = s_g * ( V_g[mb+2q][col], V_g[mb+2q+1][col] )
    unsigned long long vr[4][8];
    #pragma unroll
    for (int g = 0; g < 4; ++g) {
        const float s = (g == 2) ? 1.0f : 0.5f;
        #pragma unroll
        for (int q = 0; q < 8; ++q) {
            const float v0 = s * __ldg(&Vg[g][(j * HPF + mb + 2 * q)     * HID + col]);
            const float v1 = s * __ldg(&Vg[g][(j * HPF + mb + 2 * q + 1) * HID + col]);
            vr[g][q] = pk2(v0, v1);
        }
    }

    // ---- bias + folded masked-U input projection ----
    // NOTE: both m-halves add their base into the accumulator and the halves are
    // then SUMMED via shfl_xor(16), so the base carries an extra 0.5 factor
    // (s * 0.5) to come out exactly once. (R10 bug: base was counted twice.)
    float ua[4], ub[4], bias[4];
    #pragma unroll
    for (int g = 0; g < 4; ++g) {
        const float s = ((g == 2) ? 1.0f : 0.5f) * 0.5f;
        float a = 0.0f, bb = 0.0f;
        if (j < 16) a = __ldg(&Ug[g][j * HID + col]);
        if (j == 0) { a += __ldg(&Ug[g][16 * HID + col]); bb = __ldg(&Ug[g][17 * HID + col]); }
        if (j == 2) { a += __ldg(&Ug[g][18 * HID + col]); bb = __ldg(&Ug[g][19 * HID + col]); }
        ua[g] = s * a; ub[g] = s * bb;
        bias[g] = s * __ldg(&Bg[g][col]);
    }
    const int fa = (j == 0) ? 0 : ((j == 2) ? 2 : ((j < 16) ? j : 0));
    const int fb = (j == 0) ? 1 : ((j == 2) ? 3 : 0);   // ub==0 when unused

    const float* xq0 = x + (long long)(b0 + 0) * SEQ * INSZ;
    const float* xq1 = x + (long long)(b0 + 1) * SEQ * INSZ;
    float* outp0 = out + (long long)(b0 + 0) * SEQ * HID + col;
    float* outp1 = out + (long long)(b0 + 1) * SEQ * HID + col;

    // ---- one-time x gather into SMEM ----
    for (int i = tid; i < SEQ; i += TPB) {
        xs[0][i] = make_float2(__ldg(xq0 + i * INSZ + fa), __ldg(xq0 + i * INSZ + fb));
        xs[1][i] = make_float2(__ldg(xq1 + i * INSZ + fa), __ldg(xq1 + i * INSZ + fb));
    }
    if (tid < 2) xs[tid][SEQ] = make_float2(0.f, 0.f);
    if (tid < HPF) { hs0[tid] = 0.0f; hs1[tid] = 0.0f; }

    float h0 = 0.0f, c0 = 0.0f, h1 = 0.0f, c1 = 0.0f;
    __syncthreads();

    // prologue: acc0 for t=0 (h(-1)=0 -> base only)
    unsigned long long acc0[4];
    {
        const float2 x0 = xs[0][0];
        #pragma unroll
        for (int g = 0; g < 4; ++g)
            acc0[g] = pk2(fmaf(x0.x, ua[g], fmaf(x0.y, ub[g], bias[g])), 0.0f);
    }

    for (int t = 0; t < SEQ; ++t) {
        // ================= Phase A: matvec1(t)  ||  epilogue0(t) =================
        unsigned long long acc1[4];
        {
            const float2 x1 = xs[1][t];
            #pragma unroll
            for (int g = 0; g < 4; ++g)
                acc1[g] = pk2(fmaf(x1.x, ua[g], fmaf(x1.y, ub[g], bias[g])), 0.0f);
        }
        #pragma unroll
        for (int q4 = 0; q4 < 4; ++q4) {
            const ulonglong2 hp = *reinterpret_cast<const ulonglong2*>(hs1 + mb + 4 * q4);
            #pragma unroll
            for (int g = 0; g < 4; ++g) {
                fma2(acc1[g], hp.x, vr[g][2 * q4]);
                fma2(acc1[g], hp.y, vr[g][2 * q4 + 1]);
            }
        }
        // epilogue batch 0 (acc0 from previous phase B / prologue)
        {
            float2 p0 = upk2(acc0[0]), p1 = upk2(acc0[1]), p2 = upk2(acc0[2]), p3 = upk2(acc0[3]);
            float s0 = p0.x + p0.y, s1 = p1.x + p1.y, s2 = p2.x + p2.y, s3 = p3.x + p3.y;
            s0 += __shfl_xor_sync(0xffffffffu, s0, 16);
            s1 += __shfl_xor_sync(0xffffffffu, s1, 16);
            s2 += __shfl_xor_sync(0xffffffffu, s2, 16);
            s3 += __shfl_xor_sync(0xffffffffu, s3, 16);
            const float it = fmaf(0.5f, tanhapx(s0), 0.5f);   // params pre-scaled by 0.5
            const float ft = fmaf(0.5f, tanhapx(s1), 0.5f);
            const float tg = tanhapx(s2);
            const float ot = fmaf(0.5f, tanhapx(s3), 0.5f);
            c0 = fmaf(ft, c0, it * tg);
            h0 = ot * tanhapx(c0);
            if (ha == 0) {
                outp0[(long long)t * HID] = h0;
                hs0[n] = h0;
            }
        }
        __syncthreads();

        // ================= Phase B: matvec0(t+1)  ||  epilogue1(t) ================
        {
            const float2 x0 = xs[0][t + 1];
            #pragma unroll
            for (int g = 0; g < 4; ++g)
                acc0[g] = pk2(fmaf(x0.x, ua[g], fmaf(x0.y, ub[g], bias[g])), 0.0f);
        }
        #pragma unroll
        for (int q4 = 0; q4 < 4; ++q4) {
            const ulonglong2 hp = *reinterpret_cast<const ulonglong2*>(hs0 + mb + 4 * q4);
            #pragma unroll
            for (int g = 0; g < 4; ++g) {
                fma2(acc0[g], hp.x, vr[g][2 * q4]);
                fma2(acc0[g], hp.y, vr[g][2 * q4 + 1]);
            }
        }
        // epilogue batch 1 (acc1 from phase A)
        {
            float2 p0 = upk2(acc1[0]), p1 = upk2(acc1[1]), p2 = upk2(acc1[2]), p3 = upk2(acc1[3]);
            float s0 = p0.x + p0.y, s1 = p1.x + p1.y, s2 = p2.x + p2.y, s3 = p3.x + p3.y;
            s0 += __shfl_xor_sync(0xffffffffu, s0, 16);
            s1 += __shfl_xor_sync(0xffffffffu, s1, 16);
            s2 += __shfl_xor_sync(0xffffffffu, s2, 16);
            s3 += __shfl_xor_sync(0xffffffffu, s3, 16);
            const float it = fmaf(0.5f, tanhapx(s0), 0.5f);
            const float ft = fmaf(0.5f, tanhapx(s1), 0.5f);
            const float tg = tanhapx(s2);
            const float ot = fmaf(0.5f, tanhapx(s3), 0.5f);
            c1 = fmaf(ft, c1, it * tg);
            h1 = ot * tanhapx(c1);
            if (ha == 0) {
                outp1[(long long)t * HID] = h1;
                hs1[n] = h1;
            }
        }
        __syncthreads();
    }

    // final (h_t, c_t) appended after hidden_seq when present in output buffer
    const long long hsz = (long long)BATCHN * SEQ * HID;
    if (out_size >= hsz + 2LL * BATCHN * HID && ha == 0) {
        out[hsz + (long long)(b0 + 0) * HID + col] = h0;
        out[hsz + (long long)(b0 + 1) * HID + col] = h1;
        out[hsz + (long long)BATCHN * HID + (long long)(b0 + 0) * HID + col] = c0;
        out[hsz + (long long)BATCHN * HID + (long long)(b0 + 1) * HID + col] = c1;
    }
}

extern "C" void kernel_launch(void* const* d_in, const int* in_sizes, int n_in,
                              void* d_out, int out_size)
{
    const float* x  = (const float*)d_in[0];
    const float* Ui = (const float*)d_in[1];
    const float* Vi = (const float*)d_in[2];
    const float* bi = (const float*)d_in[3];
    const float* Uf = (const float*)d_in[4];
    const float* Vf = (const float*)d_in[5];
    const float* bf = (const float*)d_in[6];
    const float* Uc = (const float*)d_in[7];
    const float* Vc = (const float*)d_in[8];
    const float* bc = (const float*)d_in[9];
    const float* Uo = (const float*)d_in[10];
    const float* Vo = (const float*)d_in[11];
    const float* bo = (const float*)d_in[12];
    float* out = (float*)d_out;

    lstm_fused_kernel<<<NCTA, TPB>>>(
        x, Ui, Vi, bi, Uf, Vf, bf, Uc, Vc, bc, Uo, Vo, bo,
        out, (long long)out_size);
}

// round 13
// speedup vs baseline: 1.4807x; 1.4807x over previous
#include <cuda_runtime.h>

#define HPF 32
#define NBLK 20
#define HID 640
#define BATCHN 128
#define SEQ 512
#define INSZ 16
#define NB2CNT 784          // CTAs running 2 batches (units 0..1567)
#define NCTA 1776           // 784*2 + 992*1 = 2560 units; 12 warps/SM, one wave

// ---- packed fp32x2 helpers (sm_103a dual fp32) ----
__device__ __forceinline__ unsigned long long pk2(float a, float b) {
    unsigned long long r;
    asm("mov.b64 %0, {%1, %2};" : "=l"(r) : "f"(a), "f"(b));
    return r;
}
__device__ __forceinline__ float2 upk2(unsigned long long v) {
    float2 f;
    asm("mov.b64 {%0, %1}, %2;" : "=f"(f.x), "=f"(f.y) : "l"(v));
    return f;
}
__device__ __forceinline__ void fma2(unsigned long long& d,
                                     unsigned long long a, unsigned long long b) {
    asm("fma.rn.f32x2 %0, %1, %2, %0;" : "+l"(d) : "l"(a), "l"(b));
}
__device__ __forceinline__ float tanhapx(float x) {
    float r;
    asm("tanh.approx.f32 %0, %1;" : "=f"(r) : "f"(x));
    return r;
}

struct Params {
    unsigned long long vr[4][16];   // V columns, packed over m-pairs
    float ua[4], ub[4], bias[4];
    int fa, fb, col;
};

__device__ __forceinline__ void load_params(
    Params& P, int j, int lane,
    const float* __restrict__ Vi, const float* __restrict__ Vf,
    const float* __restrict__ Vc, const float* __restrict__ Vo,
    const float* __restrict__ Ui, const float* __restrict__ Uf,
    const float* __restrict__ Uc, const float* __restrict__ Uo,
    const float* __restrict__ bi, const float* __restrict__ bf,
    const float* __restrict__ bc, const float* __restrict__ bo)
{
    const float* Vg[4] = {Vi, Vf, Vc, Vo};
    const float* Ug[4] = {Ui, Uf, Uc, Uo};
    const float* Bg[4] = {bi, bf, bc, bo};
    const int col = j * HPF + lane;
    P.col = col;
    #pragma unroll
    for (int g = 0; g < 4; ++g) {
        #pragma unroll
        for (int q = 0; q < 16; ++q) {
            const float v0 = __ldg(&Vg[g][(j * HPF + 2 * q)     * HID + col]);
            const float v1 = __ldg(&Vg[g][(j * HPF + 2 * q + 1) * HID + col]);
            P.vr[g][q] = pk2(v0, v1);
        }
    }
    #pragma unroll
    for (int g = 0; g < 4; ++g) {
        float a = 0.0f, bb = 0.0f;
        if (j < 16) a = __ldg(&Ug[g][j * HID + col]);
        if (j == 0) { a += __ldg(&Ug[g][16 * HID + col]); bb = __ldg(&Ug[g][17 * HID + col]); }
        if (j == 2) { a += __ldg(&Ug[g][18 * HID + col]); bb = __ldg(&Ug[g][19 * HID + col]); }
        P.ua[g] = a; P.ub[g] = bb;
        P.bias[g] = __ldg(&Bg[g][col]);
    }
    P.fa = (j == 0) ? 0 : ((j == 2) ? 2 : ((j < 16) ? j : 0));
    P.fb = (j == 0) ? 1 : ((j == 2) ? 3 : 0);   // ub==0 when unused
}

__device__ __forceinline__ void gate_epilogue(
    const unsigned long long acc[4], float& c, float& h)
{
    const float2 pi = upk2(acc[0]);
    const float2 pf = upk2(acc[1]);
    const float2 pc = upk2(acc[2]);
    const float2 po = upk2(acc[3]);
    const float it = fmaf(0.5f, tanhapx(0.5f * (pi.x + pi.y)), 0.5f);
    const float ft = fmaf(0.5f, tanhapx(0.5f * (pf.x + pf.y)), 0.5f);
    const float tg = tanhapx(pc.x + pc.y);
    const float ot = fmaf(0.5f, tanhapx(0.5f * (po.x + po.y)), 0.5f);
    c = fmaf(ft, c, it * tg);
    h = ot * tanhapx(c);
}

__global__ __launch_bounds__(32, 12)
void lstm_fused_kernel(const float* __restrict__ x,
                       const float* __restrict__ Ui, const float* __restrict__ Vi, const float* __restrict__ bi,
                       const float* __restrict__ Uf, const float* __restrict__ Vf, const float* __restrict__ bf,
                       const float* __restrict__ Uc, const float* __restrict__ Vc, const float* __restrict__ bc,
                       const float* __restrict__ Uo, const float* __restrict__ Vo, const float* __restrict__ bo,
                       float* __restrict__ out, long long out_size)
{
    __shared__ __align__(16) float hs0[HPF];
    __shared__ __align__(16) float hs1[HPF];
    __shared__ __align__(16) float2 xs[2][SEQ + 1];

    const int lane = threadIdx.x;
    const int bid  = blockIdx.x;
    const long long hsz = (long long)BATCHN * SEQ * HID;
    const bool tails = (out_size >= hsz + 2LL * BATCHN * HID);

    Params P;

    if (bid < NB2CNT) {
        // ===================== NB=2 path (proven R9 structure) =====================
        const int u0 = 2 * bid;
        const int j  = u0 >> 7;
        const int b0 = u0 & 127;
        load_params(P, j, lane, Vi, Vf, Vc, Vo, Ui, Uf, Uc, Uo, bi, bf, bc, bo);

        const float* xq0 = x + (long long)(b0 + 0) * SEQ * INSZ;
        const float* xq1 = x + (long long)(b0 + 1) * SEQ * INSZ;
        float* outp0 = out + (long long)(b0 + 0) * SEQ * HID + P.col;
        float* outp1 = out + (long long)(b0 + 1) * SEQ * HID + P.col;

        #pragma unroll 4
        for (int i = lane; i < SEQ; i += 32) {
            xs[0][i] = make_float2(__ldg(xq0 + i * INSZ + P.fa), __ldg(xq0 + i * INSZ + P.fb));
            xs[1][i] = make_float2(__ldg(xq1 + i * INSZ + P.fa), __ldg(xq1 + i * INSZ + P.fb));
        }
        if (lane == 0) { xs[0][SEQ] = make_float2(0.f, 0.f); xs[1][SEQ] = make_float2(0.f, 0.f); }

        float h0 = 0.0f, c0 = 0.0f, h1 = 0.0f, c1 = 0.0f;
        hs0[lane] = 0.0f; hs1[lane] = 0.0f;
        __syncwarp();

        unsigned long long acc0[4];
        {
            const float2 x0 = xs[0][0];
            #pragma unroll
            for (int g = 0; g < 4; ++g)
                acc0[g] = pk2(fmaf(x0.x, P.ua[g], fmaf(x0.y, P.ub[g], P.bias[g])), 0.0f);
        }

        for (int t = 0; t < SEQ; ++t) {
            // Phase A: matvec1(t) || epilogue0(t)
            unsigned long long acc1[4];
            {
                const float2 x1 = xs[1][t];
                #pragma unroll
                for (int g = 0; g < 4; ++g)
                    acc1[g] = pk2(fmaf(x1.x, P.ua[g], fmaf(x1.y, P.ub[g], P.bias[g])), 0.0f);
            }
            #pragma unroll
            for (int q4 = 0; q4 < 4; ++q4) {
                const ulonglong2 hp = *reinterpret_cast<const ulonglong2*>(hs1 + 8 * q4);
                const ulonglong2 hq = *reinterpret_cast<const ulonglong2*>(hs1 + 8 * q4 + 4);
                #pragma unroll
                for (int g = 0; g < 4; ++g) {
                    fma2(acc1[g], hp.x, P.vr[g][4 * q4]);
                    fma2(acc1[g], hp.y, P.vr[g][4 * q4 + 1]);
                    fma2(acc1[g], hq.x, P.vr[g][4 * q4 + 2]);
                    fma2(acc1[g], hq.y, P.vr[g][4 * q4 + 3]);
                }
            }
            gate_epilogue(acc0, c0, h0);
            outp0[(long long)t * HID] = h0;
            hs0[lane] = h0;
            __syncwarp();

            // Phase B: matvec0(t+1) || epilogue1(t)
            {
                const float2 x0 = xs[0][t + 1];
                #pragma unroll
                for (int g = 0; g < 4; ++g)
                    acc0[g] = pk2(fmaf(x0.x, P.ua[g], fmaf(x0.y, P.ub[g], P.bias[g])), 0.0f);
            }
            #pragma unroll
            for (int q4 = 0; q4 < 4; ++q4) {
                const ulonglong2 hp = *reinterpret_cast<const ulonglong2*>(hs0 + 8 * q4);
                const ulonglong2 hq = *reinterpret_cast<const ulonglong2*>(hs0 + 8 * q4 + 4);
                #pragma unroll
                for (int g = 0; g < 4; ++g) {
                    fma2(acc0[g], hp.x, P.vr[g][4 * q4]);
                    fma2(acc0[g], hp.y, P.vr[g][4 * q4 + 1]);
                    fma2(acc0[g], hq.x, P.vr[g][4 * q4 + 2]);
                    fma2(acc0[g], hq.y, P.vr[g][4 * q4 + 3]);
                }
            }
            gate_epilogue(acc1, c1, h1);
            outp1[(long long)t * HID] = h1;
            hs1[lane] = h1;
            __syncwarp();
        }

        if (tails) {
            out[hsz + (long long)(b0 + 0) * HID + P.col] = h0;
            out[hsz + (long long)(b0 + 1) * HID + P.col] = h1;
            out[hsz + (long long)BATCHN * HID + (long long)(b0 + 0) * HID + P.col] = c0;
            out[hsz + (long long)BATCHN * HID + (long long)(b0 + 1) * HID + P.col] = c1;
        }
    } else {
        // ===================== NB=1 path (lean single chain) =====================
        const int u  = 2 * NB2CNT + (bid - NB2CNT);    // 1568..2559
        const int j  = u >> 7;
        const int b  = u & 127;
        load_params(P, j, lane, Vi, Vf, Vc, Vo, Ui, Uf, Uc, Uo, bi, bf, bc, bo);

        const float* xq = x + (long long)b * SEQ * INSZ;
        float* outp = out + (long long)b * SEQ * HID + P.col;

        #pragma unroll 4
        for (int i = lane; i < SEQ; i += 32) {
            xs[0][i] = make_float2(__ldg(xq + i * INSZ + P.fa), __ldg(xq + i * INSZ + P.fb));
        }

        float h = 0.0f, c = 0.0f;
        hs0[lane] = 0.0f;
        __syncwarp();

        for (int t = 0; t < SEQ; ++t) {
            const float2 xt = xs[0][t];
            unsigned long long acc[4];
            #pragma unroll
            for (int g = 0; g < 4; ++g)
                acc[g] = pk2(fmaf(xt.x, P.ua[g], fmaf(xt.y, P.ub[g], P.bias[g])), 0.0f);

            #pragma unroll
            for (int q4 = 0; q4 < 4; ++q4) {
                const ulonglong2 hp = *reinterpret_cast<const ulonglong2*>(hs0 + 8 * q4);
                const ulonglong2 hq = *reinterpret_cast<const ulonglong2*>(hs0 + 8 * q4 + 4);
                #pragma unroll
                for (int g = 0; g < 4; ++g) {
                    fma2(acc[g], hp.x, P.vr[g][4 * q4]);
                    fma2(acc[g], hp.y, P.vr[g][4 * q4 + 1]);
                    fma2(acc[g], hq.x, P.vr[g][4 * q4 + 2]);
                    fma2(acc[g], hq.y, P.vr[g][4 * q4 + 3]);
                }
            }

            gate_epilogue(acc, c, h);
            outp[(long long)t * HID] = h;
            hs0[lane] = h;        // all reads of h(t-1) precede this in program order
            __syncwarp();          // fence before next step's reads
        }

        if (tails) {
            out[hsz + (long long)b * HID + P.col] = h;
            out[hsz + (long long)BATCHN * HID + (long long)b * HID + P.col] = c;
        }
    }
}

extern "C" void kernel_launch(void* const* d_in, const int* in_sizes, int n_in,
                              void* d_out, int out_size)
{
    const float* x  = (const float*)d_in[0];
    const float* Ui = (const float*)d_in[1];
    const float* Vi = (const float*)d_in[2];
    const float* bi = (const float*)d_in[3];
    const float* Uf = (const float*)d_in[4];
    const float* Vf = (const float*)d_in[5];
    const float* bf = (const float*)d_in[6];
    const float* Uc = (const float*)d_in[7];
    const float* Vc = (const float*)d_in[8];
    const float* bc = (const float*)d_in[9];
    const float* Uo = (const float*)d_in[10];
    const float* Vo = (const float*)d_in[11];
    const float* bo = (const float*)d_in[12];
    float* out = (float*)d_out;

    lstm_fused_kernel<<<NCTA, 32>>>(
        x, Ui, Vi, bi, Uf, Vf, bf, Uc, Vc, bc, Uo, Vo, bo,
        out, (long long)out_size);
}